// round 12
// baseline (speedup 1.0000x reference)
#include <cuda_runtime.h>
#include <cooperative_groups.h>
#include <cstdint>
#include <math.h>

namespace cg = cooperative_groups;

#define BLOCK 512
#define CLUSTER 8
#define CAP 12

// shared-memory layout (floats). Per CTA: 32 e-columns.
#define OFF_X0    0        // 3072  X buffer A: [d 0..255][h 0..11]
#define OFF_X1    3072     // 3072  X buffer B
#define OFF_SCAL  6144     // 96    per-stage column scales [3][32]
#define OFF_CNT   6240     // 32    per-column bucket count (int)
#define OFF_COLK  6272     // 384   bucket packed (k<<8|d7) (int) [32][CAP]
#define OFF_COLC6 6656     // 384   bucket c6 (int) [32][CAP]
#define OFF_COLCV 7040     // 1152  correction values [3][32][CAP]
#define OFF_P4T   8192     // 256   p4 row for b
#define OFF_P11T  8448     // 256   p11 row for b
#define OFF_P14T  8704     // 256   p14 row for b
#define OFF_P1T   8960     // 8192  p1 slice [256 d][32 e]; overwritten by M in stage 0
#define OFF_P3T   17152    // 8192  p3 slice [256 d][32 e]
#define OFF_RED   25344    // 6144  partials [16 dch][12 h][32 e]
#define OFF_SCAN  31488    // 8192  scan arrays p5/p7/p8/p6 (int)
#define SMEM_FLOATS 39680
#define SMEM_BYTES (SMEM_FLOATS * 4)   // 158,720 B

#define S5_OFF (OFF_SCAN + 0)
#define S7_OFF (OFF_SCAN + 2048)
#define S8_OFF (OFF_SCAN + 4096)
#define S6_OFF (OFF_SCAN + 6144)

extern __shared__ float smem[];

__device__ __forceinline__ void cp_async16(uint32_t saddr, const void* gptr) {
    asm volatile("cp.async.cg.shared.global [%0], [%1], 16;\n"
                 :: "r"(saddr), "l"(gptr));
}

__global__ void __cluster_dims__(CLUSTER, 1, 1) __launch_bounds__(BLOCK, 1)
chain_kernel(const float* __restrict__ p1, const float* __restrict__ p2,
             const float* __restrict__ p3, const float* __restrict__ p4,
             const int* __restrict__ p5, const int* __restrict__ p6,
             const int* __restrict__ p7, const int* __restrict__ p8,
             const float* __restrict__ p9, const float* __restrict__ p10,
             const float* __restrict__ p11, const float* __restrict__ p12,
             const float* __restrict__ p13, const float* __restrict__ p14,
             const float* __restrict__ p15, const float* __restrict__ p16,
             float* __restrict__ out, int K)
{
    cg::cluster_group cluster = cg::this_cluster();
    const int tid  = (int)threadIdx.x;
    const int rank = (int)cluster.block_rank();   // e-segment 0..7
    const int b    = (int)blockIdx.x >> 3;        // batch 0..5
    const int e0   = rank * 32;

    float* X0     = smem + OFF_X0;
    float* X1     = smem + OFF_X1;
    float* scal   = smem + OFF_SCAL;
    float* colcv  = smem + OFF_COLCV;
    float* p1t    = smem + OFF_P1T;
    float* p3t    = smem + OFF_P3T;
    float* red    = smem + OFF_RED;
    int*   colcnt = (int*)(smem + OFF_CNT);
    int*   colk   = (int*)(smem + OFF_COLK);
    int*   colc6  = (int*)(smem + OFF_COLC6);
    const int* s5 = (const int*)(smem + S5_OFF);
    const int* s7 = (const int*)(smem + S7_OFF);
    const int* s8 = (const int*)(smem + S8_OFF);
    const int* s6 = (const int*)(smem + S6_OFF);

    const int KC = (K < 2048) ? K : 2048;

    // ---- A: single cp.async burst for EVERYTHING the kernel reads later ----
    {
        uint32_t sb = (uint32_t)__cvta_generic_to_shared(smem);
        // index arrays: 4 x 512 chunks
        const int* isrc[4] = { p5, p7, p8, p6 };
        #pragma unroll
        for (int it = 0; it < 4; it++) {
            int idx = tid + it * BLOCK;
            int a = idx >> 9, c = idx & 511;
            if (c * 4 < KC)
                cp_async16(sb + (OFF_SCAN + a * 2048 + c * 4) * 4, isrc[a] + c * 4);
        }
        // p1/p3 slices: 2048 chunks each (row d, quad q)
        const float* g1 = p1 + b * 65536 + e0;
        const float* g3 = p3 + b * 65536 + e0;
        #pragma unroll
        for (int it = 0; it < 4; it++) {
            int idx = tid + it * BLOCK;
            int row = idx >> 3, q = (idx & 7) << 2;
            cp_async16(sb + (OFF_P1T + row * 32 + q) * 4, g1 + row * 256 + q);
            cp_async16(sb + (OFF_P3T + row * 32 + q) * 4, g3 + row * 256 + q);
        }
        // p4/p11/p14 rows: 64 chunks each
        if (tid < 192) {
            int a = tid / 64, c = (tid % 64) << 2;
            const float* gs = (a == 0) ? p4 : (a == 1) ? p11 : p14;
            cp_async16(sb + (OFF_P4T + a * 256 + c) * 4, gs + b * 256 + c);
        }
        asm volatile("cp.async.commit_group;\n" ::: "memory");
    }

    // ---- B: counters, X0 transpose-load, mod scales (overlap the copies) ----
    if (tid < 32) colcnt[tid] = 0;

    for (int i = tid; i < 3072; i += BLOCK) {     // 6 iters, coalesced
        int h = i >> 8, d = i & 255;
        X0[d * 12 + h] = p2[h * 1536 + b * 256 + d];
    }

    if (tid < 32) {
        float fr[3] = { p9[0],  p12[0], p15[0] };
        float ph[3] = { p10[0], p13[0], p16[0] };
        float t = (float)(e0 + tid);
        #pragma unroll
        for (int s = 0; s < 3; s++) {
            float a  = t * 6.2831853071795864f;
            a = a * fr[s] + ph[s];
            float sv = sinf(a);
            float m  = sv * sv * 0.1f + 0.95f;
            scal[s * 32 + tid] = (s == 1) ? m : (1.0f / m);
        }
    }

    asm volatile("cp.async.wait_group 0;\n" ::: "memory");
    __syncthreads();    // all smem inputs visible

    // ---- C: single-pass scan -> per-column buckets (pure smem) ----
    #pragma unroll
    for (int it = 0; it < 4; it++) {
        int k = tid + it * BLOCK;
        if (k < KC && s5[k] == b) {
            int e8 = s8[k];
            if ((e8 >> 5) == rank) {
                int c = e8 & 31;
                int j = atomicAdd(&colcnt[c], 1);
                if (j < CAP) {
                    colk[c * CAP + j]  = (k << 8) | s7[k];
                    colc6[c * CAP + j] = s6[k];
                }
            }
        }
    }
    __syncthreads();

    // ---- D: winner resolution + correction values (pure smem) ----
    if (tid < 32 * CAP) {
        int c = tid / CAP, j = tid % CAP;
        int n = colcnt[c]; if (n > CAP) n = CAP;
        if (j < n) {
            int me = colk[c * CAP + j];
            bool win = true;
            for (int j2 = 0; j2 < n; j2++) {
                int oth = colk[c * CAP + j2];
                if (((oth ^ me) & 255) == 0 && oth > me) { win = false; break; }
            }
            if (win) {
                int d7 = me & 255, c6 = colc6[tid];
                float pb = p1t[d7 * 32 + c];              // smem
                colcv[0 * 384 + tid] = smem[OFF_P4T  + c6] - pb;
                colcv[1 * 384 + tid] = smem[OFF_P11T + c6] - pb;
                colcv[2 * 384 + tid] = smem[OFF_P14T + c6] - pb;
            } else {
                colcv[0 * 384 + tid] = 0.0f;
                colcv[1 * 384 + tid] = 0.0f;
                colcv[2 * 384 + tid] = 0.0f;
            }
        }
    }
    __syncthreads();    // p1t may now be overwritten by M

    // ---- thread mapping: 16 d-chunks x 32 e-columns ----
    const int dch = tid >> 5;      // 0..15 (16 d each)
    const int el  = tid & 31;      // single e-column

    float* McB = p1t + dch * 16 * 32 + el;     // own cells only
    float* P3B = p3t + dch * 16 * 32 + el;

    // ---- 3-stage chain, fully smem-resident ----
    for (int s = 0; s < 3; s++) {
        const float* Xin  = (s & 1) ? X1 : X0;
        float*       Xout = (s & 1) ? X0 : X1;

        float acc[12];
        #pragma unroll
        for (int i = 0; i < 12; i++) acc[i] = 0.0f;

        const float4* X4 = (const float4*)(Xin + dch * 16 * 12);

        if (s == 0) {
            #pragma unroll
            for (int i = 0; i < 16; i++) {
                float m = fmaf(P3B[i * 32], 0.975f, McB[i * 32]);
                McB[i * 32] = m;               // cache M in place (own cell)
                float4 xa = X4[i * 3 + 0];
                float4 xb = X4[i * 3 + 1];
                float4 xc = X4[i * 3 + 2];
                acc[0]  += xa.x * m;  acc[1]  += xa.y * m;
                acc[2]  += xa.z * m;  acc[3]  += xa.w * m;
                acc[4]  += xb.x * m;  acc[5]  += xb.y * m;
                acc[6]  += xb.z * m;  acc[7]  += xb.w * m;
                acc[8]  += xc.x * m;  acc[9]  += xc.y * m;
                acc[10] += xc.z * m;  acc[11] += xc.w * m;
            }
        } else {
            #pragma unroll
            for (int i = 0; i < 16; i++) {
                float m = McB[i * 32];
                float4 xa = X4[i * 3 + 0];
                float4 xb = X4[i * 3 + 1];
                float4 xc = X4[i * 3 + 2];
                acc[0]  += xa.x * m;  acc[1]  += xa.y * m;
                acc[2]  += xa.z * m;  acc[3]  += xa.w * m;
                acc[4]  += xb.x * m;  acc[5]  += xb.y * m;
                acc[6]  += xb.z * m;  acc[7]  += xb.w * m;
                acc[8]  += xc.x * m;  acc[9]  += xc.y * m;
                acc[10] += xc.z * m;  acc[11] += xc.w * m;
            }
        }

        // write partials: red[dch][h][el]
        #pragma unroll
        for (int h = 0; h < 12; h++)
            red[(dch * 12 + h) * 32 + el] = acc[h];
        __syncthreads();

        // reduce 16 partials + corrections + scale; push result to all 8 CTAs
        if (tid < 384) {
            int h = tid >> 5, c = tid & 31;
            float sum = 0.0f;
            #pragma unroll
            for (int dc = 0; dc < 16; dc++) sum += red[(dc * 12 + h) * 32 + c];

            int n = colcnt[c]; if (n > CAP) n = CAP;
            for (int j = 0; j < n; j++) {
                int d7 = colk[c * CAP + j] & 255;
                sum += Xin[d7 * 12 + h] * colcv[s * 384 + c * CAP + j];
            }
            sum *= scal[s * 32 + c];

            if (s < 2) {
                float* dst = Xout + (e0 + c) * 12 + h;   // same offset in every CTA
                #pragma unroll
                for (int p = 0; p < CLUSTER; p++)
                    *cluster.map_shared_rank(dst, p) = sum;   // incl. self
            } else {
                out[h * 1536 + b * 256 + e0 + c] = sum;
            }
        }

        if (s < 2) cluster.sync();   // remote stores complete + full-CTA barrier
    }
}

extern "C" void kernel_launch(void* const* d_in, const int* in_sizes, int n_in,
                              void* d_out, int out_size)
{
    (void)n_in; (void)out_size;
    cudaFuncSetAttribute(chain_kernel,
                         cudaFuncAttributeMaxDynamicSharedMemorySize, SMEM_BYTES);
    chain_kernel<<<6 * CLUSTER, BLOCK, SMEM_BYTES>>>(
        (const float*)d_in[0],  (const float*)d_in[1],
        (const float*)d_in[2],  (const float*)d_in[3],
        (const int*)  d_in[4],  (const int*)  d_in[5],
        (const int*)  d_in[6],  (const int*)  d_in[7],
        (const float*)d_in[8],  (const float*)d_in[9],
        (const float*)d_in[10], (const float*)d_in[11],
        (const float*)d_in[12], (const float*)d_in[13],
        (const float*)d_in[14], (const float*)d_in[15],
        (float*)d_out, in_sizes[4]);
}

// round 13
// speedup vs baseline: 1.0993x; 1.0993x over previous
#include <cuda_runtime.h>
#include <cooperative_groups.h>
#include <cstdint>
#include <math.h>

namespace cg = cooperative_groups;

#define BLOCK 512
#define CLUSTER 8
#define CAP 12

// shared-memory layout (floats). Per CTA: 6 heads, 32 e-columns.
#define OFF_X0    0        // 2048  X buffer A: [d 0..255][8 (6 h + 2 pad)]
#define OFF_X1    2048     // 2048  X buffer B
#define OFF_SCAL  4096     // 96    per-stage column scales [3][32]
#define OFF_CNT   4192     // 32    per-column bucket count (int)
#define OFF_COLK  4224     // 384   bucket packed (k<<8|d7) (int) [32][CAP]
#define OFF_COLC6 4608     // 384   bucket c6 (int) [32][CAP]
#define OFF_COLCV 4992     // 1152  correction values [3][32][CAP]
#define OFF_P4T   6144     // 256   p4 row for b
#define OFF_P11T  6400     // 256   p11 row for b
#define OFF_P14T  6656     // 256   p14 row for b
#define OFF_P1T   6912     // 8192  p1 slice [256 d][32 e]; becomes M in stage 0
#define OFF_P3T   15104    // 8192  p3 slice [256 d][32 e]
#define OFF_RED   23296    // 3072  partials [16 dch][6 h][32 e]
#define SMEM_FLOATS 26368
#define SMEM_BYTES (SMEM_FLOATS * 4)   // 105,472 B  (x2 CTAs/SM = 211 KB)

extern __shared__ float smem[];

__device__ __forceinline__ void cp_async16(uint32_t saddr, const void* gptr) {
    asm volatile("cp.async.cg.shared.global [%0], [%1], 16;\n"
                 :: "r"(saddr), "l"(gptr));
}

__global__ void __cluster_dims__(CLUSTER, 1, 1) __launch_bounds__(BLOCK, 2)
chain_kernel(const float* __restrict__ p1, const float* __restrict__ p2,
             const float* __restrict__ p3, const float* __restrict__ p4,
             const int* __restrict__ p5, const int* __restrict__ p6,
             const int* __restrict__ p7, const int* __restrict__ p8,
             const float* __restrict__ p9, const float* __restrict__ p10,
             const float* __restrict__ p11, const float* __restrict__ p12,
             const float* __restrict__ p13, const float* __restrict__ p14,
             const float* __restrict__ p15, const float* __restrict__ p16,
             float* __restrict__ out, int K)
{
    cg::cluster_group cluster = cg::this_cluster();
    const int tid  = (int)threadIdx.x;
    const int rank = (int)cluster.block_rank();   // e-segment 0..7
    const int cid  = (int)blockIdx.x >> 3;        // 0..11
    const int b    = cid >> 1;                    // batch 0..5
    const int h0   = (cid & 1) * 6;               // head-group base
    const int e0   = rank * 32;

    float* X0     = smem + OFF_X0;
    float* X1     = smem + OFF_X1;
    float* scal   = smem + OFF_SCAL;
    float* colcv  = smem + OFF_COLCV;
    float* p1t    = smem + OFF_P1T;
    float* p3t    = smem + OFF_P3T;
    float* red    = smem + OFF_RED;
    int*   colcnt = (int*)(smem + OFF_CNT);
    int*   colk   = (int*)(smem + OFF_COLK);
    int*   colc6  = (int*)(smem + OFF_COLC6);

    const int KC = (K < 2048) ? K : 2048;

    // ---- A: cp.async burst: p1/p3 slices + gather rows ----
    {
        uint32_t sb = (uint32_t)__cvta_generic_to_shared(smem);
        const float* g1 = p1 + b * 65536 + e0;
        const float* g3 = p3 + b * 65536 + e0;
        #pragma unroll
        for (int it = 0; it < 4; it++) {
            int idx = tid + it * BLOCK;
            int row = idx >> 3, q = (idx & 7) << 2;
            cp_async16(sb + (OFF_P1T + row * 32 + q) * 4, g1 + row * 256 + q);
            cp_async16(sb + (OFF_P3T + row * 32 + q) * 4, g3 + row * 256 + q);
        }
        if (tid < 192) {
            int a = tid / 64, c = (tid % 64) << 2;
            const float* gs = (a == 0) ? p4 : (a == 1) ? p11 : p14;
            cp_async16(sb + (OFF_P4T + a * 256 + c) * 4, gs + b * 256 + c);
        }
        asm volatile("cp.async.commit_group;\n" ::: "memory");
    }

    // ---- B: counters, X0 transpose-load (6 heads), mod scales ----
    if (tid < 32) colcnt[tid] = 0;

    for (int i = tid; i < 1536; i += BLOCK) {     // 3 iters
        int h = i >> 8, d = i & 255;
        X0[d * 8 + h] = p2[(h0 + h) * 1536 + b * 256 + d];
    }

    if (tid < 32) {
        float fr[3] = { p9[0],  p12[0], p15[0] };
        float ph[3] = { p10[0], p13[0], p16[0] };
        float t = (float)(e0 + tid);
        #pragma unroll
        for (int s = 0; s < 3; s++) {
            float a  = t * 6.2831853071795864f;
            a = a * fr[s] + ph[s];
            float sv = sinf(a);
            float m  = sv * sv * 0.1f + 0.95f;
            scal[s * 32 + tid] = (s == 1) ? m : (1.0f / m);
        }
    }
    __syncthreads();   // counters + X0 visible before scan/buckets

    // ---- C: scan from GLOBAL -> per-column buckets ----
    #pragma unroll
    for (int it = 0; it < 4; it++) {
        int k = tid + it * BLOCK;
        if (k < KC && __ldg(p5 + k) == b) {
            int e8 = __ldg(p8 + k);
            if ((e8 >> 5) == rank) {
                int c = e8 & 31;
                int j = atomicAdd(&colcnt[c], 1);
                if (j < CAP) {
                    colk[c * CAP + j]  = (k << 8) | __ldg(p7 + k);
                    colc6[c * CAP + j] = __ldg(p6 + k);
                }
            }
        }
    }
    asm volatile("cp.async.wait_group 0;\n" ::: "memory");
    __syncthreads();   // buckets + slices + gather rows visible

    // ---- D: winner resolution + correction values (pure smem) ----
    if (tid < 32 * CAP) {
        int c = tid / CAP, j = tid % CAP;
        int n = colcnt[c]; if (n > CAP) n = CAP;
        if (j < n) {
            int me = colk[c * CAP + j];
            bool win = true;
            for (int j2 = 0; j2 < n; j2++) {
                int oth = colk[c * CAP + j2];
                if (((oth ^ me) & 255) == 0 && oth > me) { win = false; break; }
            }
            if (win) {
                int d7 = me & 255, c6 = colc6[tid];
                float pb = p1t[d7 * 32 + c];
                colcv[0 * 384 + tid] = smem[OFF_P4T  + c6] - pb;
                colcv[1 * 384 + tid] = smem[OFF_P11T + c6] - pb;
                colcv[2 * 384 + tid] = smem[OFF_P14T + c6] - pb;
            } else {
                colcv[0 * 384 + tid] = 0.0f;
                colcv[1 * 384 + tid] = 0.0f;
                colcv[2 * 384 + tid] = 0.0f;
            }
        }
    }
    __syncthreads();   // p1t may now be overwritten by M

    // ---- thread mapping: 16 d-chunks x 32 e-columns ----
    const int dch = tid >> 5;      // 0..15 (16 d each)
    const int el  = tid & 31;

    float* McB = p1t + dch * 16 * 32 + el;     // own cells only
    float* P3B = p3t + dch * 16 * 32 + el;

    // ---- 3-stage chain, fully smem-resident ----
    for (int s = 0; s < 3; s++) {
        const float* Xin  = (s & 1) ? X1 : X0;
        float*       Xout = (s & 1) ? X0 : X1;

        float acc[6];
        #pragma unroll
        for (int i = 0; i < 6; i++) acc[i] = 0.0f;

        const float4* X4 = (const float4*)(Xin + dch * 16 * 8);

        if (s == 0) {
            #pragma unroll
            for (int i = 0; i < 16; i++) {
                float m = fmaf(P3B[i * 32], 0.975f, McB[i * 32]);
                McB[i * 32] = m;               // cache M in place
                float4 xa = X4[i * 2 + 0];     // h0..h3
                float4 xb = X4[i * 2 + 1];     // h4,h5,(pad,pad)
                acc[0] += xa.x * m;  acc[1] += xa.y * m;
                acc[2] += xa.z * m;  acc[3] += xa.w * m;
                acc[4] += xb.x * m;  acc[5] += xb.y * m;
            }
        } else {
            #pragma unroll
            for (int i = 0; i < 16; i++) {
                float m = McB[i * 32];
                float4 xa = X4[i * 2 + 0];
                float4 xb = X4[i * 2 + 1];
                acc[0] += xa.x * m;  acc[1] += xa.y * m;
                acc[2] += xa.z * m;  acc[3] += xa.w * m;
                acc[4] += xb.x * m;  acc[5] += xb.y * m;
            }
        }

        // write partials: red[dch][h][el]
        #pragma unroll
        for (int h = 0; h < 6; h++)
            red[(dch * 6 + h) * 32 + el] = acc[h];
        __syncthreads();

        // reduce 16 partials + corrections + scale; push to all 8 CTAs
        if (tid < 192) {
            int h = tid >> 5, c = tid & 31;
            float sum = 0.0f;
            #pragma unroll
            for (int dc = 0; dc < 16; dc++) sum += red[(dc * 6 + h) * 32 + c];

            int n = colcnt[c]; if (n > CAP) n = CAP;
            for (int j = 0; j < n; j++) {
                int d7 = colk[c * CAP + j] & 255;
                sum += Xin[d7 * 8 + h] * colcv[s * 384 + c * CAP + j];
            }
            sum *= scal[s * 32 + c];

            if (s < 2) {
                float* dst = Xout + (e0 + c) * 8 + h;   // same offset in every CTA
                #pragma unroll
                for (int p = 0; p < CLUSTER; p++)
                    *cluster.map_shared_rank(dst, p) = sum;   // incl. self
            } else {
                out[(h0 + h) * 1536 + b * 256 + e0 + c] = sum;
            }
        }

        if (s < 2) cluster.sync();   // remote stores complete + full-CTA barrier
    }
}

extern "C" void kernel_launch(void* const* d_in, const int* in_sizes, int n_in,
                              void* d_out, int out_size)
{
    (void)n_in; (void)out_size;
    cudaFuncSetAttribute(chain_kernel,
                         cudaFuncAttributeMaxDynamicSharedMemorySize, SMEM_BYTES);
    chain_kernel<<<6 * 2 * CLUSTER, BLOCK, SMEM_BYTES>>>(
        (const float*)d_in[0],  (const float*)d_in[1],
        (const float*)d_in[2],  (const float*)d_in[3],
        (const int*)  d_in[4],  (const int*)  d_in[5],
        (const int*)  d_in[6],  (const int*)  d_in[7],
        (const float*)d_in[8],  (const float*)d_in[9],
        (const float*)d_in[10], (const float*)d_in[11],
        (const float*)d_in[12], (const float*)d_in[13],
        (const float*)d_in[14], (const float*)d_in[15],
        (float*)d_out, in_sizes[4]);
}